// round 15
// baseline (speedup 1.0000x reference)
#include <cuda_runtime.h>
#include <math.h>
#include <cstdint>

#define L    2048
#define D    768
#define KF   24
#define KD   (KF * D)        /* 18432 */
#define JT   23              /* FIR truncation (24 taps, 3x8 split-K) */
#define DD   (D * D)
#define LQ4  2184            /* padded length of each shifted filter copy */

#define NS   3               /* cp.async pipeline stages (BK=32) */
#define TPB  256

/* SMEM per stage (floats): A 128 rows x 36 (144B stride) + B 128 rows x 36 = 9216 */
#define STAGE_F 9216
#define SMEM_SZ (NS * STAGE_F * 4)     /* 110592 B, 2 CTA/SM */

/* ---------------- scratch (device globals; no allocation allowed) ---------------- */
__device__ float g_vq4[KF * 4 * LQ4];      /* 4 shifted copies of reversed filter:
                                              vq4[k][s][t] = vq_k[t-s], 0-padded  */
__device__ float g_uR[L * D];              /* tf32 u, row-major (AR A-operand)     */
__device__ float g_uT[D * L];              /* tf32 u^T (conv B-operand)            */
__device__ float g_phiT[(size_t)D * KD];   /* tf32 m_phi^T [768][18432]            */
__device__ float g_xt[(size_t)L * KD];     /* x_tilde [l][k*D+d]                   */
__device__ float g_delta[L * D];           /* delta_phi + delta_ar_u               */
__device__ float g_H[(JT + 1) * DD];       /* H_j = Phi_j bank (row-major)         */
__device__ float g_Gm[DD];                 /* scratch: G_{m-1} = H_{m-1}^T         */
__device__ float g_m2[DD];                 /* M2 row-major (tf32)                  */
__device__ float g_muTT[D * 3 * D];        /* [o][lag*768+i] = m_u[o][i][lag]      */
__device__ float g_AB[D * 2 * D];          /* [G_m | RT] rows (doubling Bt)        */
__device__ float g_part[5 * L * D];        /* split-K partial outputs              */

/* ---------------- helpers ---------------- */
__device__ __forceinline__ uint32_t s2u(const void* p) {
    uint32_t a;
    asm("{ .reg .u64 t; cvta.to.shared.u64 t, %1; cvt.u32.u64 %0, t; }" : "=r"(a) : "l"(p));
    return a;
}
__device__ __forceinline__ float tf32r(float x) {      /* round-to-nearest tf32 */
    float r; asm("cvt.rna.tf32.f32 %0, %1;" : "=f"(r) : "f"(x)); return r;
}

/* ---------------- small prep kernels ---------------- */
/* vq4[k][s][t] = vp_k[L-1-(t-s)] for t-s in [0,L), else 0 (reversed + shifted) */
__global__ void prep_vq4(const float* __restrict__ evals, const float* __restrict__ evecs) {
    int idx = blockIdx.x * blockDim.x + threadIdx.x;
    if (idx >= KF * 4 * LQ4) return;
    int k = idx / (4 * LQ4);
    int rem = idx - k * (4 * LQ4);
    int s = rem / LQ4, t = rem - s * LQ4;
    int tv = t - s;
    float v = 0.f;
    if (tv >= 0 && tv < L)
        v = tf32r(evecs[(L - 1 - tv) * KF + k] * powf(evals[k], 0.25f));
    g_vq4[idx] = v;
}

__global__ void round_arr(const float* __restrict__ s, float* __restrict__ d, int n) {
    int i = blockIdx.x * blockDim.x + threadIdx.x;
    if (i < n) d[i] = tf32r(s[i]);
}

__global__ void prep_mats(const float* __restrict__ m_y, const float* __restrict__ m_u) {
    int idx = blockIdx.x * blockDim.x + threadIdx.x;
    if (idx >= DD) return;
    int o = idx / D, i = idx - o * D;
    g_m2[idx]     = tf32r(m_y[(o * 2 + 1) * D + i]);   /* M2 row-major */
    g_H[DD + idx] = tf32r(m_y[(o * 2 + 0) * D + i]);   /* H_1 = M1     */
    g_H[idx]      = (i == o) ? 1.f : 0.f;              /* H_0 = I      */
#pragma unroll
    for (int lag = 0; lag < 3; lag++)
        g_muTT[(size_t)o * (3 * D) + lag * D + i] =
            tf32r(m_u[((size_t)o * D + i) * 3 + lag]);
}

/* tiled transpose: dst[c][r] = src[r][c]; grid (cols/32, rows/32), block (32,8) */
__global__ void transp(const float* __restrict__ s, float* __restrict__ d,
                       int lds, int ldd, int rnd) {
    __shared__ float t[32][33];
    int bx = blockIdx.x * 32, by = blockIdx.y * 32;
    int tx = threadIdx.x, ty = threadIdx.y;
#pragma unroll
    for (int i = 0; i < 4; i++)
        t[ty + i * 8][tx] = s[(size_t)(by + ty + i * 8) * lds + bx + tx];
    __syncthreads();
#pragma unroll
    for (int i = 0; i < 4; i++) {
        float v = t[tx][ty + i * 8];
        if (rnd) v = tf32r(v);
        d[(size_t)(bx + ty + i * 8) * ldd + by + tx] = v;
    }
}

/* reduce np split-K partials (stride L*D) -> out; optional tf32 round */
__global__ void reduce_p(const float* __restrict__ p, int np, float* __restrict__ out, int rnd) {
    int i = blockIdx.x * blockDim.x + threadIdx.x;
    if (i >= (L * D) / 4) return;
    float4 s = ((const float4*)p)[i];
    for (int z = 1; z < np; z++) {
        float4 v = ((const float4*)(p + (size_t)z * L * D))[i];
        s.x += v.x; s.y += v.y; s.z += v.z; s.w += v.w;
    }
    if (rnd) { s.x = tf32r(s.x); s.y = tf32r(s.y); s.z = tf32r(s.z); s.w = tf32r(s.w); }
    ((float4*)out)[i] = s;
}

/* ---------------- mma.sync tf32 GEMM: C[128x128 tile] = op(A) @ B ----------------
   8 warps, 2x4 layout, warp tile 64m x 32n (2 CTA/SM, ~128 regs).
   B transposed globally (Bt[n][k]), n-major SMEM, fragments via ldmatrix b16-pair.
   MODE 0: A[row][k0+k] plain.
   MODE 1: per-K-slab A offset: j = jzs*z + k0/D; addr -= j*jmul; if causal,
           zero-fill when row0+r-j < 0 (jmul=lda: row shift; jmul=DD: matrix hop).
   MODE 2: Toeplitz A row r = vq[o..o+31], o = L+1-row0-r+k0, served 16B-aligned
           from shifted copy s = (-o)&3 of vq4 -> plain 16B cp.async, no predicates;
           triangular Kend; y-blocks reversed (heavy-first).                      */
template <int MODE>
__global__ void __launch_bounds__(TPB, 2)
tgemm(const float* __restrict__ A, const float* __restrict__ B, float* __restrict__ C,
      int K, int lda, int ldbt, int ldc, int rnd, int jzs, int jmul, int causal,
      int bjmul, int aB, int bB, int cB) {
    extern __shared__ float sm[];
    A += (size_t)blockIdx.z * aB;
    B += (size_t)blockIdx.z * bB;
    C += (size_t)blockIdx.z * cB;
    const int jbase = jzs * blockIdx.z;

    const int yb = (MODE == 2) ? (gridDim.y - 1 - blockIdx.y) : blockIdx.y;
    const int row0 = yb * 128, col0 = blockIdx.x * 128;
    const int tid = threadIdx.x, lane = tid & 31, wid = tid >> 5;
    const int wm = wid & 1, wn = wid >> 1;       /* warp tile: 64 rows x 32 cols */
    const int g = lane >> 2, tig = lane & 3;

    const int Kend = (MODE == 2) ? min(K, row0 + 128) : K;
    const int T = Kend >> 5;

    float c[4][4][4];
#pragma unroll
    for (int a = 0; a < 4; a++)
#pragma unroll
        for (int b = 0; b < 4; b++)
#pragma unroll
            for (int e = 0; e < 4; e++) c[a][b][e] = 0.f;

    auto load_stage = [&](int st, int k0) {
        float* As = sm + st * STAGE_F;
        uint32_t abase = s2u(As), bbase = abase + 4608 * 4;
        /* A tile: 128 rows x 32 k (144B row stride), 1024 16B chunks */
        if (MODE == 2) {
            const int obase = L + 1 - row0 + k0;   /* vq index of A[r=0][k=0] */
#pragma unroll
            for (int q = 0; q < 4; q++) {
                int id = tid + q * 256;
                int r = id >> 3, c8 = id & 7;
                uint32_t dst = abase + r * 144 + c8 * 16;
                int o = obase - r;
                int s = (-o) & 3;                  /* o+s ≡ 0 mod 4 -> 16B aligned */
                const float* src = A + (size_t)s * LQ4 + (o + s) + c8 * 4;
                asm volatile("cp.async.cg.shared.global [%0], [%1], 16;"
                             :: "r"(dst), "l"(src) : "memory");
            }
        } else {
#pragma unroll
            for (int q = 0; q < 4; q++) {
                int id = tid + q * 256;
                int r = id >> 3, c8 = id & 7;
                uint32_t dst = abase + r * 144 + c8 * 16;
                if (MODE == 1) {
                    int jq = k0 / D;
                    int j = jbase + jq;
                    int colb = k0 - jq * D;
                    long off = (long)(row0 + r) * lda + colb + c8 * 4 - (long)j * jmul;
                    uint32_t sz = (!causal || (row0 + r - j >= 0)) ? 16u : 0u;
                    const float* src = A + (sz ? off : 0);
                    asm volatile("cp.async.cg.shared.global [%0], [%1], 16, %2;"
                                 :: "r"(dst), "l"(src), "r"(sz) : "memory");
                } else {
                    const float* src = A + (size_t)(row0 + r) * lda + k0 + c8 * 4;
                    asm volatile("cp.async.cg.shared.global [%0], [%1], 16;"
                                 :: "r"(dst), "l"(src) : "memory");
                }
            }
        }
        /* B tile (n-major): 128 n-rows x 32 k (144B row stride), 1024 chunks */
        {
            int jB = k0 / D;
#pragma unroll
            for (int q = 0; q < 4; q++) {
                int id = tid + q * 256;
                int r = id >> 3, c8 = id & 7;
                uint32_t dst = bbase + r * 144 + c8 * 16;
                const float* src = B + (size_t)(col0 + r) * ldbt + k0 + c8 * 4
                                 + (size_t)jB * bjmul;
                asm volatile("cp.async.cg.shared.global [%0], [%1], 16;"
                             :: "r"(dst), "l"(src) : "memory");
            }
        }
    };

    /* prologue */
#pragma unroll
    for (int s = 0; s < NS - 1; s++) {
        if (s < T) load_stage(s, s * 32);
        asm volatile("cp.async.commit_group;" ::: "memory");
    }

    for (int t = 0; t < T; t++) {
        asm volatile("cp.async.wait_group %0;" :: "n"(NS - 2) : "memory");
        __syncthreads();
        if (t + NS - 1 < T) load_stage((t + NS - 1) % NS, (t + NS - 1) * 32);
        asm volatile("cp.async.commit_group;" ::: "memory");

        float* As = sm + (t % NS) * STAGE_F;
        uint32_t abase = s2u(As);
        uint32_t bbase = abase + 4608 * 4;
        /* B ldmatrix per-warp base: grp = lane>>3 selects (n half, k chunk) */
        const int grp = lane >> 3, l8 = lane & 7;
        uint32_t bB0 = bbase + (wn * 32 + (grp >> 1) * 8 + l8) * 144 + (grp & 1) * 16;
#pragma unroll
        for (int kst = 0; kst < 4; kst++) {
            uint32_t af[4][4];
#pragma unroll
            for (int mt = 0; mt < 4; mt++) {
                uint32_t addr = abase + (wm * 64 + mt * 16 + (lane & 15)) * 144
                              + kst * 32 + ((lane >> 4) << 4);
                asm volatile("ldmatrix.sync.aligned.m8n8.x4.shared.b16 {%0,%1,%2,%3}, [%4];"
                    : "=r"(af[mt][0]), "=r"(af[mt][1]), "=r"(af[mt][2]), "=r"(af[mt][3])
                    : "r"(addr));
            }
            uint32_t bf[4][2];
            asm volatile("ldmatrix.sync.aligned.m8n8.x4.shared.b16 {%0,%1,%2,%3}, [%4];"
                : "=r"(bf[0][0]), "=r"(bf[0][1]), "=r"(bf[1][0]), "=r"(bf[1][1])
                : "r"(bB0 + kst * 32));
            asm volatile("ldmatrix.sync.aligned.m8n8.x4.shared.b16 {%0,%1,%2,%3}, [%4];"
                : "=r"(bf[2][0]), "=r"(bf[2][1]), "=r"(bf[3][0]), "=r"(bf[3][1])
                : "r"(bB0 + 2304 + kst * 32));
#pragma unroll
            for (int mt = 0; mt < 4; mt++)
#pragma unroll
                for (int nt = 0; nt < 4; nt++)
                    asm volatile("mma.sync.aligned.m16n8k8.row.col.f32.tf32.tf32.f32 "
                        "{%0,%1,%2,%3},{%4,%5,%6,%7},{%8,%9},{%0,%1,%2,%3};"
                        : "+f"(c[mt][nt][0]), "+f"(c[mt][nt][1]),
                          "+f"(c[mt][nt][2]), "+f"(c[mt][nt][3])
                        : "r"(af[mt][0]), "r"(af[mt][1]), "r"(af[mt][2]), "r"(af[mt][3]),
                          "r"(bf[nt][0]), "r"(bf[nt][1]));
        }
    }

    /* epilogue */
#pragma unroll
    for (int mt = 0; mt < 4; mt++)
#pragma unroll
        for (int nt = 0; nt < 4; nt++) {
            int rr = row0 + wm * 64 + mt * 16 + g;
            int cc = col0 + wn * 32 + nt * 8 + tig * 2;
            float2 v0 = make_float2(c[mt][nt][0], c[mt][nt][1]);
            float2 v1 = make_float2(c[mt][nt][2], c[mt][nt][3]);
            if (rnd) {
                v0.x = tf32r(v0.x); v0.y = tf32r(v0.y);
                v1.x = tf32r(v1.x); v1.y = tf32r(v1.y);
            }
            *(float2*)&C[(size_t)rr * ldc + cc] = v0;
            *(float2*)&C[(size_t)(rr + 8) * ldc + cc] = v1;
        }
}

/* ---------------- launch ---------------- */
extern "C" void kernel_launch(void* const* d_in, const int* in_sizes, int n_in,
                              void* d_out, int out_size) {
    const float* u      = (const float*)d_in[0];   /* [2048, 768]   */
    const float* m_y    = (const float*)d_in[1];   /* [768, 2, 768] */
    const float* m_u    = (const float*)d_in[2];   /* [768, 768, 3] */
    const float* m_phi  = (const float*)d_in[3];   /* [18432, 768]  */
    const float* evals  = (const float*)d_in[4];   /* [24]          */
    const float* evecs  = (const float*)d_in[5];   /* [2048, 24]    */
    float* y = (float*)d_out;                      /* [2048, 768]   */

    float *pvq4, *puR, *puT, *pphiT, *pxt, *pdl, *pH, *pGm, *pm2, *pmuTT, *pab, *pP;
    cudaGetSymbolAddress((void**)&pvq4,  g_vq4);
    cudaGetSymbolAddress((void**)&puR,   g_uR);
    cudaGetSymbolAddress((void**)&puT,   g_uT);
    cudaGetSymbolAddress((void**)&pphiT, g_phiT);
    cudaGetSymbolAddress((void**)&pxt,   g_xt);
    cudaGetSymbolAddress((void**)&pdl,   g_delta);
    cudaGetSymbolAddress((void**)&pH,    g_H);
    cudaGetSymbolAddress((void**)&pGm,   g_Gm);
    cudaGetSymbolAddress((void**)&pm2,   g_m2);
    cudaGetSymbolAddress((void**)&pmuTT, g_muTT);
    cudaGetSymbolAddress((void**)&pab,   g_AB);
    cudaGetSymbolAddress((void**)&pP,    g_part);

    cudaFuncSetAttribute(tgemm<0>, cudaFuncAttributeMaxDynamicSharedMemorySize, SMEM_SZ);
    cudaFuncSetAttribute(tgemm<1>, cudaFuncAttributeMaxDynamicSharedMemorySize, SMEM_SZ);
    cudaFuncSetAttribute(tgemm<2>, cudaFuncAttributeMaxDynamicSharedMemorySize, SMEM_SZ);

    cudaStream_t s1;
    cudaEvent_t evF, evP, evU, ev1;
    cudaStreamCreateWithFlags(&s1, cudaStreamNonBlocking);
    cudaEventCreateWithFlags(&evF, cudaEventDisableTiming);
    cudaEventCreateWithFlags(&evP, cudaEventDisableTiming);
    cudaEventCreateWithFlags(&evU, cudaEventDisableTiming);
    cudaEventCreateWithFlags(&ev1, cudaEventDisableTiming);

    cudaEventRecord(evF, 0);
    cudaStreamWaitEvent(s1, evF, 0);

    /* ---- stream 0: input-dependent chain ---- */
    prep_vq4 <<<(KF * 4 * LQ4 + 255) / 256, 256>>>(evals, evecs);
    round_arr<<<(L * D + 255) / 256, 256>>>(u, puR, L * D);
    transp<<<dim3(D / 32, L / 32), dim3(32, 8)>>>(u, puT, D, L, 1);   /* uT, rounded */
    cudaEventRecord(evU, 0);

    /* conv: X_k = Toeplitz(vp_k) @ U (triangular); A from shifted filter copies */
    tgemm<2><<<dim3(D / 128, L / 128, KF), TPB, SMEM_SZ>>>(
        pvq4, puT, pxt, L, 0, L, KD, 1, 0, 0, 0, 0, 4 * LQ4, 0, D);

    /* ---- stream 1: weight-only chain ---- */
    transp<<<dim3(D / 32, KD / 32), dim3(32, 8), 0, s1>>>(m_phi, pphiT, D, KD, 1);
    cudaEventRecord(evP, s1);
    prep_mats<<<(DD + 255) / 256, 256, 0, s1>>>(m_y, m_u);

    /* Phi bank doubling: H_{m+i} = [H_i|H_{i-1}] @ [H_m ; M2 H_{m-1}],
       transposed fixed-B = [G_m | RT], RT = G_{m-1} @ M2^T (Bt = M2).
       Last stage builds only up to H_23 (batch 7).                      */
    const int mv[5] = {1, 2, 4, 8, 16};
    const int bc[5] = {1, 2, 4, 8, 7};
    for (int s = 0; s < 5; s++) {
        int m = mv[s];
        transp<<<dim3(D / 32, D / 32), dim3(32, 8), 0, s1>>>(
            pH + (size_t)(m - 1) * DD, pGm, D, D, 0);           /* G_{m-1} */
        transp<<<dim3(D / 32, D / 32), dim3(32, 8), 0, s1>>>(
            pH + (size_t)m * DD, pab, D, 2 * D, 0);             /* G_m -> AB left */
        tgemm<0><<<dim3(D / 128, D / 128), TPB, SMEM_SZ, s1>>>( /* RT -> AB right */
            pGm, pm2, pab + D, D, D, D, 2 * D, 1, 0, 0, 0, 0, 0, 0, 0);
        tgemm<1><<<dim3(D / 128, D / 128, bc[s]), TPB, SMEM_SZ, s1>>>(
            pH + DD, pab, pH + (size_t)(m + 1) * DD, 2 * D, D, 2 * D, D,
            1, 0, DD, 0, 0, DD, 0, DD);
    }
    /* delta_ar_u -> partial 3 (A = uR causal-multishift, Bt = muTT) */
    cudaStreamWaitEvent(s1, evU, 0);
    tgemm<1><<<dim3(D / 128, L / 128), TPB, SMEM_SZ, s1>>>(
        puR, pmuTT, pP + (size_t)3 * L * D, 3 * D, D, 3 * D, D,
        0, 0, D, 1, 0, 0, 0, 0);
    cudaEventRecord(ev1, s1);

    /* ---- stream 0: phi GEMM (Bt = m_phi^T), split-K x3 ---- */
    cudaStreamWaitEvent(0, evP, 0);
    tgemm<0><<<dim3(D / 128, L / 128, 3), TPB, SMEM_SZ>>>(
        pxt, pphiT, pP, KD / 3, KD, KD, D, 0, 0, 0, 0, 0, KD / 3, KD / 3, L * D);

    cudaStreamWaitEvent(0, ev1, 0);
    reduce_p<<<(L * D / 4 + 255) / 256, 256>>>(pP, 4, pdl, 1);

    /* y = sum_{j=0}^{23} shift_j(delta) @ Phi_j^T : Bt = H bank, 3x8 split */
    tgemm<1><<<dim3(D / 128, L / 128, 3), TPB, SMEM_SZ>>>(
        pdl, pH, pP, 8 * D, D, D, D, 0, 8, D, 1, DD - D, 0, 8 * DD, L * D);
    reduce_p<<<(L * D / 4 + 255) / 256, 256>>>(pP, 3, y, 0);
}

// round 17
// speedup vs baseline: 1.5705x; 1.5705x over previous
#include <cuda_runtime.h>
#include <math.h>
#include <cstdint>

#define L    2048
#define D    768
#define KF   24
#define KD   (KF * D)        /* 18432 */
#define JT   23              /* FIR truncation (24 taps, 3x8 split-K) */
#define DD   (D * D)

#define NS   3               /* cp.async pipeline stages (BK=32) */
#define TPB  256

/* SMEM per stage (floats): A 128 rows x 36 (144B stride) + B 128 rows x 36 = 9216 */
#define STAGE_F 9216
#define SMEM_SZ (NS * STAGE_F * 4)     /* 110592 B, 2 CTA/SM */

/* ---------------- scratch (device globals; no allocation allowed) ---------------- */
__device__ float g_vpT[KF * L];            /* filters * eig^(1/4), [k][t], tf32    */
__device__ float g_uR[L * D];              /* tf32 u, row-major (AR A-operand)     */
__device__ float g_uT[D * L];              /* tf32 u^T (conv B-operand)            */
__device__ float g_phiT[(size_t)D * KD];   /* tf32 m_phi^T [768][18432]            */
__device__ float g_xt[(size_t)L * KD];     /* x_tilde [l][k*D+d]                   */
__device__ float g_delta[L * D];           /* delta_phi + delta_ar_u               */
__device__ float g_H[(JT + 1) * DD];       /* H_j = Phi_j bank (row-major)         */
__device__ float g_Gm[DD];                 /* scratch: G_{m-1} = H_{m-1}^T         */
__device__ float g_m2[DD];                 /* M2 row-major (tf32)                  */
__device__ float g_muTT[D * 3 * D];        /* [o][lag*768+i] = m_u[o][i][lag]      */
__device__ float g_AB[D * 2 * D];          /* [G_m | RT] rows (doubling Bt)        */
__device__ float g_part[5 * L * D];        /* split-K partial outputs              */

/* ---------------- helpers ---------------- */
__device__ __forceinline__ uint32_t s2u(const void* p) {
    uint32_t a;
    asm("{ .reg .u64 t; cvta.to.shared.u64 t, %1; cvt.u32.u64 %0, t; }" : "=r"(a) : "l"(p));
    return a;
}
__device__ __forceinline__ float tf32r(float x) {      /* round-to-nearest tf32 */
    float r; asm("cvt.rna.tf32.f32 %0, %1;" : "=f"(r) : "f"(x)); return r;
}

/* ---------------- small prep kernels ---------------- */
__global__ void prep_vp(const float* __restrict__ evals, const float* __restrict__ evecs) {
    int idx = blockIdx.x * blockDim.x + threadIdx.x;
    if (idx >= L * KF) return;
    int t = idx / KF, k = idx - t * KF;
    g_vpT[k * L + t] = tf32r(evecs[idx] * powf(evals[k], 0.25f));
}

__global__ void round_arr(const float* __restrict__ s, float* __restrict__ d, int n) {
    int i = blockIdx.x * blockDim.x + threadIdx.x;
    if (i < n) d[i] = tf32r(s[i]);
}

__global__ void prep_mats(const float* __restrict__ m_y, const float* __restrict__ m_u) {
    int idx = blockIdx.x * blockDim.x + threadIdx.x;
    if (idx >= DD) return;
    int o = idx / D, i = idx - o * D;
    g_m2[idx]     = tf32r(m_y[(o * 2 + 1) * D + i]);   /* M2 row-major */
    g_H[DD + idx] = tf32r(m_y[(o * 2 + 0) * D + i]);   /* H_1 = M1     */
    g_H[idx]      = (i == o) ? 1.f : 0.f;              /* H_0 = I      */
#pragma unroll
    for (int lag = 0; lag < 3; lag++)
        g_muTT[(size_t)o * (3 * D) + lag * D + i] =
            tf32r(m_u[((size_t)o * D + i) * 3 + lag]);
}

/* tiled transpose: dst[c][r] = src[r][c]; grid (cols/32, rows/32), block (32,8) */
__global__ void transp(const float* __restrict__ s, float* __restrict__ d,
                       int lds, int ldd, int rnd) {
    __shared__ float t[32][33];
    int bx = blockIdx.x * 32, by = blockIdx.y * 32;
    int tx = threadIdx.x, ty = threadIdx.y;
#pragma unroll
    for (int i = 0; i < 4; i++)
        t[ty + i * 8][tx] = s[(size_t)(by + ty + i * 8) * lds + bx + tx];
    __syncthreads();
#pragma unroll
    for (int i = 0; i < 4; i++) {
        float v = t[tx][ty + i * 8];
        if (rnd) v = tf32r(v);
        d[(size_t)(bx + ty + i * 8) * ldd + by + tx] = v;
    }
}

/* reduce np split-K partials (stride L*D) -> out; optional tf32 round */
__global__ void reduce_p(const float* __restrict__ p, int np, float* __restrict__ out, int rnd) {
    int i = blockIdx.x * blockDim.x + threadIdx.x;
    if (i >= (L * D) / 4) return;
    float4 s = ((const float4*)p)[i];
    for (int z = 1; z < np; z++) {
        float4 v = ((const float4*)(p + (size_t)z * L * D))[i];
        s.x += v.x; s.y += v.y; s.z += v.z; s.w += v.w;
    }
    if (rnd) { s.x = tf32r(s.x); s.y = tf32r(s.y); s.z = tf32r(s.z); s.w = tf32r(s.w); }
    ((float4*)out)[i] = s;
}

/* ---------------- mma.sync tf32 GEMM: C[128x128 tile] = op(A) @ B ----------------
   8 warps, 2x4 layout, warp tile 64m x 32n (2 CTA/SM, ~128 regs).
   B transposed globally (Bt[n][k]), n-major SMEM, fragments via ldmatrix b16-pair.
   MODE 0: A[row][k0+k] plain.
   MODE 1: per-K-slab A offset: j = jzs*z + k0/D; addr -= j*jmul; if causal,
           zero-fill when row0+r-j < 0 (jmul=lda: row shift; jmul=DD: matrix hop).
   MODE 2: Toeplitz A from vp (forward layout): A[r][k] = vp[row0+r-2-k], built
           with predicated sync LDG + float4 STS (R10 path: best measured);
           triangular Kend; y-blocks reversed (heavy-first).                      */
template <int MODE>
__global__ void __launch_bounds__(TPB, 2)
tgemm(const float* __restrict__ A, const float* __restrict__ B, float* __restrict__ C,
      int K, int lda, int ldbt, int ldc, int rnd, int jzs, int jmul, int causal,
      int bjmul, int aB, int bB, int cB) {
    extern __shared__ float sm[];
    A += (size_t)blockIdx.z * aB;
    B += (size_t)blockIdx.z * bB;
    C += (size_t)blockIdx.z * cB;
    const int jbase = jzs * blockIdx.z;

    const int yb = (MODE == 2) ? (gridDim.y - 1 - blockIdx.y) : blockIdx.y;
    const int row0 = yb * 128, col0 = blockIdx.x * 128;
    const int tid = threadIdx.x, lane = tid & 31, wid = tid >> 5;
    const int wm = wid & 1, wn = wid >> 1;       /* warp tile: 64 rows x 32 cols */
    const int g = lane >> 2, tig = lane & 3;

    const int Kend = (MODE == 2) ? min(K, row0 + 128) : K;
    const int T = Kend >> 5;

    float c[4][4][4];
#pragma unroll
    for (int a = 0; a < 4; a++)
#pragma unroll
        for (int b = 0; b < 4; b++)
#pragma unroll
            for (int e = 0; e < 4; e++) c[a][b][e] = 0.f;

    auto load_stage = [&](int st, int k0) {
        float* As = sm + st * STAGE_F;
        uint32_t abase = s2u(As), bbase = abase + 4608 * 4;
        /* A tile: 128 rows x 32 k (144B row stride), 1024 16B chunks */
        if (MODE == 2) {
#pragma unroll
            for (int q = 0; q < 4; q++) {
                int id = tid + q * 256;
                int r = id >> 3, c8 = id & 7;
                int kk = k0 + c8 * 4;
                int t0 = row0 + r - 2 - kk;
                float4 v;
                v.x = (t0 >= 0) ? A[t0]     : 0.f;
                v.y = (t0 >= 1) ? A[t0 - 1] : 0.f;
                v.z = (t0 >= 2) ? A[t0 - 2] : 0.f;
                v.w = (t0 >= 3) ? A[t0 - 3] : 0.f;
                *(float4*)((char*)As + r * 144 + c8 * 16) = v;
            }
        } else {
#pragma unroll
            for (int q = 0; q < 4; q++) {
                int id = tid + q * 256;
                int r = id >> 3, c8 = id & 7;
                uint32_t dst = abase + r * 144 + c8 * 16;
                if (MODE == 1) {
                    int jq = k0 / D;
                    int j = jbase + jq;
                    int colb = k0 - jq * D;
                    long off = (long)(row0 + r) * lda + colb + c8 * 4 - (long)j * jmul;
                    uint32_t sz = (!causal || (row0 + r - j >= 0)) ? 16u : 0u;
                    const float* src = A + (sz ? off : 0);
                    asm volatile("cp.async.cg.shared.global [%0], [%1], 16, %2;"
                                 :: "r"(dst), "l"(src), "r"(sz) : "memory");
                } else {
                    const float* src = A + (size_t)(row0 + r) * lda + k0 + c8 * 4;
                    asm volatile("cp.async.cg.shared.global [%0], [%1], 16;"
                                 :: "r"(dst), "l"(src) : "memory");
                }
            }
        }
        /* B tile (n-major): 128 n-rows x 32 k (144B row stride), 1024 chunks */
        {
            int jB = k0 / D;
#pragma unroll
            for (int q = 0; q < 4; q++) {
                int id = tid + q * 256;
                int r = id >> 3, c8 = id & 7;
                uint32_t dst = bbase + r * 144 + c8 * 16;
                const float* src = B + (size_t)(col0 + r) * ldbt + k0 + c8 * 4
                                 + (size_t)jB * bjmul;
                asm volatile("cp.async.cg.shared.global [%0], [%1], 16;"
                             :: "r"(dst), "l"(src) : "memory");
            }
        }
    };

    /* prologue */
#pragma unroll
    for (int s = 0; s < NS - 1; s++) {
        if (s < T) load_stage(s, s * 32);
        asm volatile("cp.async.commit_group;" ::: "memory");
    }

    for (int t = 0; t < T; t++) {
        asm volatile("cp.async.wait_group %0;" :: "n"(NS - 2) : "memory");
        __syncthreads();
        if (t + NS - 1 < T) load_stage((t + NS - 1) % NS, (t + NS - 1) * 32);
        asm volatile("cp.async.commit_group;" ::: "memory");

        float* As = sm + (t % NS) * STAGE_F;
        uint32_t abase = s2u(As);
        uint32_t bbase = abase + 4608 * 4;
        /* B ldmatrix per-warp base: grp = lane>>3 selects (n half, k chunk) */
        const int grp = lane >> 3, l8 = lane & 7;
        uint32_t bB0 = bbase + (wn * 32 + (grp >> 1) * 8 + l8) * 144 + (grp & 1) * 16;
#pragma unroll
        for (int kst = 0; kst < 4; kst++) {
            uint32_t af[4][4];
#pragma unroll
            for (int mt = 0; mt < 4; mt++) {
                uint32_t addr = abase + (wm * 64 + mt * 16 + (lane & 15)) * 144
                              + kst * 32 + ((lane >> 4) << 4);
                asm volatile("ldmatrix.sync.aligned.m8n8.x4.shared.b16 {%0,%1,%2,%3}, [%4];"
                    : "=r"(af[mt][0]), "=r"(af[mt][1]), "=r"(af[mt][2]), "=r"(af[mt][3])
                    : "r"(addr));
            }
            uint32_t bf[4][2];
            asm volatile("ldmatrix.sync.aligned.m8n8.x4.shared.b16 {%0,%1,%2,%3}, [%4];"
                : "=r"(bf[0][0]), "=r"(bf[0][1]), "=r"(bf[1][0]), "=r"(bf[1][1])
                : "r"(bB0 + kst * 32));
            asm volatile("ldmatrix.sync.aligned.m8n8.x4.shared.b16 {%0,%1,%2,%3}, [%4];"
                : "=r"(bf[2][0]), "=r"(bf[2][1]), "=r"(bf[3][0]), "=r"(bf[3][1])
                : "r"(bB0 + 2304 + kst * 32));
#pragma unroll
            for (int mt = 0; mt < 4; mt++)
#pragma unroll
                for (int nt = 0; nt < 4; nt++)
                    asm volatile("mma.sync.aligned.m16n8k8.row.col.f32.tf32.tf32.f32 "
                        "{%0,%1,%2,%3},{%4,%5,%6,%7},{%8,%9},{%0,%1,%2,%3};"
                        : "+f"(c[mt][nt][0]), "+f"(c[mt][nt][1]),
                          "+f"(c[mt][nt][2]), "+f"(c[mt][nt][3])
                        : "r"(af[mt][0]), "r"(af[mt][1]), "r"(af[mt][2]), "r"(af[mt][3]),
                          "r"(bf[nt][0]), "r"(bf[nt][1]));
        }
    }

    /* epilogue */
#pragma unroll
    for (int mt = 0; mt < 4; mt++)
#pragma unroll
        for (int nt = 0; nt < 4; nt++) {
            int rr = row0 + wm * 64 + mt * 16 + g;
            int cc = col0 + wn * 32 + nt * 8 + tig * 2;
            float2 v0 = make_float2(c[mt][nt][0], c[mt][nt][1]);
            float2 v1 = make_float2(c[mt][nt][2], c[mt][nt][3]);
            if (rnd) {
                v0.x = tf32r(v0.x); v0.y = tf32r(v0.y);
                v1.x = tf32r(v1.x); v1.y = tf32r(v1.y);
            }
            *(float2*)&C[(size_t)rr * ldc + cc] = v0;
            *(float2*)&C[(size_t)(rr + 8) * ldc + cc] = v1;
        }
}

/* ---------------- launch ---------------- */
extern "C" void kernel_launch(void* const* d_in, const int* in_sizes, int n_in,
                              void* d_out, int out_size) {
    const float* u      = (const float*)d_in[0];   /* [2048, 768]   */
    const float* m_y    = (const float*)d_in[1];   /* [768, 2, 768] */
    const float* m_u    = (const float*)d_in[2];   /* [768, 768, 3] */
    const float* m_phi  = (const float*)d_in[3];   /* [18432, 768]  */
    const float* evals  = (const float*)d_in[4];   /* [24]          */
    const float* evecs  = (const float*)d_in[5];   /* [2048, 24]    */
    float* y = (float*)d_out;                      /* [2048, 768]   */

    float *pvp, *puR, *puT, *pphiT, *pxt, *pdl, *pH, *pGm, *pm2, *pmuTT, *pab, *pP;
    cudaGetSymbolAddress((void**)&pvp,   g_vpT);
    cudaGetSymbolAddress((void**)&puR,   g_uR);
    cudaGetSymbolAddress((void**)&puT,   g_uT);
    cudaGetSymbolAddress((void**)&pphiT, g_phiT);
    cudaGetSymbolAddress((void**)&pxt,   g_xt);
    cudaGetSymbolAddress((void**)&pdl,   g_delta);
    cudaGetSymbolAddress((void**)&pH,    g_H);
    cudaGetSymbolAddress((void**)&pGm,   g_Gm);
    cudaGetSymbolAddress((void**)&pm2,   g_m2);
    cudaGetSymbolAddress((void**)&pmuTT, g_muTT);
    cudaGetSymbolAddress((void**)&pab,   g_AB);
    cudaGetSymbolAddress((void**)&pP,    g_part);

    cudaFuncSetAttribute(tgemm<0>, cudaFuncAttributeMaxDynamicSharedMemorySize, SMEM_SZ);
    cudaFuncSetAttribute(tgemm<1>, cudaFuncAttributeMaxDynamicSharedMemorySize, SMEM_SZ);
    cudaFuncSetAttribute(tgemm<2>, cudaFuncAttributeMaxDynamicSharedMemorySize, SMEM_SZ);

    cudaStream_t s1;
    cudaEvent_t evF, evP, evU, ev1;
    cudaStreamCreateWithFlags(&s1, cudaStreamNonBlocking);
    cudaEventCreateWithFlags(&evF, cudaEventDisableTiming);
    cudaEventCreateWithFlags(&evP, cudaEventDisableTiming);
    cudaEventCreateWithFlags(&evU, cudaEventDisableTiming);
    cudaEventCreateWithFlags(&ev1, cudaEventDisableTiming);

    cudaEventRecord(evF, 0);
    cudaStreamWaitEvent(s1, evF, 0);

    /* ---- stream 0: input-dependent chain ---- */
    prep_vp  <<<(L * KF + 255) / 256, 256>>>(evals, evecs);
    round_arr<<<(L * D + 255) / 256, 256>>>(u, puR, L * D);
    transp<<<dim3(D / 32, L / 32), dim3(32, 8)>>>(u, puT, D, L, 1);   /* uT, rounded */
    cudaEventRecord(evU, 0);

    /* conv: X_k = Toeplitz(vp_k) @ U (triangular); A built from forward filter */
    tgemm<2><<<dim3(D / 128, L / 128, KF), TPB, SMEM_SZ>>>(
        pvp, puT, pxt, L, 0, L, KD, 1, 0, 0, 0, 0, L, 0, D);

    /* ---- stream 1: weight-only chain ---- */
    transp<<<dim3(D / 32, KD / 32), dim3(32, 8), 0, s1>>>(m_phi, pphiT, D, KD, 1);
    cudaEventRecord(evP, s1);
    prep_mats<<<(DD + 255) / 256, 256, 0, s1>>>(m_y, m_u);

    /* Phi bank doubling: H_{m+i} = [H_i|H_{i-1}] @ [H_m ; M2 H_{m-1}],
       transposed fixed-B = [G_m | RT], RT = G_{m-1} @ M2^T (Bt = M2).
       Last stage builds only up to H_23 (batch 7).                      */
    const int mv[5] = {1, 2, 4, 8, 16};
    const int bc[5] = {1, 2, 4, 8, 7};
    for (int s = 0; s < 5; s++) {
        int m = mv[s];
        transp<<<dim3(D / 32, D / 32), dim3(32, 8), 0, s1>>>(
            pH + (size_t)(m - 1) * DD, pGm, D, D, 0);           /* G_{m-1} */
        transp<<<dim3(D / 32, D / 32), dim3(32, 8), 0, s1>>>(
            pH + (size_t)m * DD, pab, D, 2 * D, 0);             /* G_m -> AB left */
        tgemm<0><<<dim3(D / 128, D / 128), TPB, SMEM_SZ, s1>>>( /* RT -> AB right */
            pGm, pm2, pab + D, D, D, D, 2 * D, 1, 0, 0, 0, 0, 0, 0, 0);
        tgemm<1><<<dim3(D / 128, D / 128, bc[s]), TPB, SMEM_SZ, s1>>>(
            pH + DD, pab, pH + (size_t)(m + 1) * DD, 2 * D, D, 2 * D, D,
            1, 0, DD, 0, 0, DD, 0, DD);
    }
    /* delta_ar_u -> partial 3 (A = uR causal-multishift, Bt = muTT) */
    cudaStreamWaitEvent(s1, evU, 0);
    tgemm<1><<<dim3(D / 128, L / 128), TPB, SMEM_SZ, s1>>>(
        puR, pmuTT, pP + (size_t)3 * L * D, 3 * D, D, 3 * D, D,
        0, 0, D, 1, 0, 0, 0, 0);
    cudaEventRecord(ev1, s1);

    /* ---- stream 0: phi GEMM (Bt = m_phi^T), split-K x3 ---- */
    cudaStreamWaitEvent(0, evP, 0);
    tgemm<0><<<dim3(D / 128, L / 128, 3), TPB, SMEM_SZ>>>(
        pxt, pphiT, pP, KD / 3, KD, KD, D, 0, 0, 0, 0, 0, KD / 3, KD / 3, L * D);

    cudaStreamWaitEvent(0, ev1, 0);
    reduce_p<<<(L * D / 4 + 255) / 256, 256>>>(pP, 4, pdl, 1);

    /* y = sum_{j=0}^{23} shift_j(delta) @ Phi_j^T : Bt = H bank, 3x8 split */
    tgemm<1><<<dim3(D / 128, L / 128, 3), TPB, SMEM_SZ>>>(
        pdl, pH, pP, 8 * D, D, D, D, 0, 8, D, 1, DD - D, 0, 8 * DD, L * D);
    reduce_p<<<(L * D / 4 + 255) / 256, 256>>>(pP, 3, y, 0);
}